// round 12
// baseline (speedup 1.0000x reference)
#include <cuda_runtime.h>

#define DIMC 192
#define BB   4
#define HH   256
#define WW   256
#define RR   48
#define KK9  9
#define EPSV 1e-5f
#define NCTA   592              // 4 x 148: exactly 4 CTAs/SM, all resident
#define NPLANE (BB * DIMC)      // 768
#define CH     32               // rows per chunk job
#define CHUNKS (HH / CH)        // 8 chunks per plane
#define NJOB   (NPLANE * CHUNKS)// 6144 jobs per phase -> 10.4 jobs/CTA

// Scratch (allocation-free rule: __device__ globals; zero-initialized)
__device__ float g_part[NJOB];      // per-chunk partial sums (deterministic)
__device__ unsigned g_arrive;
__device__ unsigned g_done;

// ---- 256-bit L2 eviction-hinted accesses ----------------------------------
__device__ __forceinline__ void ld256_evict_last(const float* p, float* v) {
    asm volatile("ld.global.L2::evict_last.v8.b32 {%0,%1,%2,%3,%4,%5,%6,%7}, [%8];"
                 : "=f"(v[0]), "=f"(v[1]), "=f"(v[2]), "=f"(v[3]),
                   "=f"(v[4]), "=f"(v[5]), "=f"(v[6]), "=f"(v[7])
                 : "l"(p));
}
__device__ __forceinline__ void ld256_evict_first(const float* p, float* v) {
    asm volatile("ld.global.L2::evict_first.v8.b32 {%0,%1,%2,%3,%4,%5,%6,%7}, [%8];"
                 : "=f"(v[0]), "=f"(v[1]), "=f"(v[2]), "=f"(v[3]),
                   "=f"(v[4]), "=f"(v[5]), "=f"(v[6]), "=f"(v[7])
                 : "l"(p));
}
__device__ __forceinline__ void st256_evict_first(float* p, const float* v) {
    asm volatile("st.global.L2::evict_first.v8.b32 [%0], {%1,%2,%3,%4,%5,%6,%7,%8};"
                 :: "l"(p),
                    "f"(v[0]), "f"(v[1]), "f"(v[2]), "f"(v[3]),
                    "f"(v[4]), "f"(v[5]), "f"(v[6]), "f"(v[7])
                 : "memory");
}

// ---------------------------------------------------------------------------
// Fused persistent kernel, 4 CTAs/SM (32 warps/SM for DRAM latency hiding) +
// fine-grained static partition (32-row chunk jobs, ~6% imbalance):
//   pool chunk-jobs (ascending) -> grid barrier -> reduce+MLP -> conv
//   chunk-jobs (descending: most recently pooled = L2-hottest first).
// ---------------------------------------------------------------------------
__global__ __launch_bounds__(256, 4) void fused_kernel(
    const float* __restrict__ x,
    const float* __restrict__ w1,
    const float* __restrict__ gamma,
    const float* __restrict__ beta,
    const float* __restrict__ rmean,
    const float* __restrict__ rvar,
    const float* __restrict__ w2,
    const float* __restrict__ b2,
    const float* __restrict__ bias,
    float* __restrict__ out) {

    const int tid  = threadIdx.x;
    const int warp = tid >> 5;
    const int lane = tid & 31;
    const int cta  = blockIdx.x;

    __shared__ float pooled_sh[NPLANE];  // 3 KB per-plane means
    __shared__ float tsh[BB * RR];       // hidden vectors, all 4 batches
    __shared__ float wsh[4];             // live taps of current conv job
    __shared__ float red[8];             // reduction scratch

    const int nmy = (cta < (NJOB % NCTA)) ? (NJOB / NCTA + 1) : (NJOB / NCTA);

    // ---------------- Phase 1: pool partial sums (evict_last pins x) -------
    for (int i = 0; i < nmy; i++) {
        const int j     = cta + i * NCTA;        // ascending in time
        const int plane = j >> 3;
        const int chunk = j & 7;
        const float* __restrict__ p =
            x + (size_t)plane * HH * WW + (size_t)chunk * CH * WW;

        float s = 0.f;
        // CH*WW = 8192 floats = 1024 float8 / 256 threads = 4 independent loads
        #pragma unroll
        for (int it = 0; it < 4; it++) {
            float v[8];
            ld256_evict_last(p + (it * 256 + tid) * 8, v);
            s += ((v[0] + v[1]) + (v[2] + v[3])) + ((v[4] + v[5]) + (v[6] + v[7]));
        }
        #pragma unroll
        for (int o = 16; o > 0; o >>= 1) s += __shfl_down_sync(0xffffffffu, s, o);
        if (lane == 0) red[warp] = s;
        __syncthreads();
        if (tid < 8) {
            float v = red[tid];
            #pragma unroll
            for (int o = 4; o > 0; o >>= 1) v += __shfl_down_sync(0xffu, v, o);
            if (tid == 0) g_part[j] = v;
        }
        __syncthreads();
    }

    // ---------------- Grid-wide barrier ------------------------------------
    if (tid == 0) {
        __threadfence();
        atomicAdd(&g_arrive, 1u);
        while (*(volatile unsigned*)&g_arrive < (unsigned)NCTA) { __nanosleep(64); }
        __threadfence();
    }
    __syncthreads();

    // ---------------- Phase 2: deterministic reduce + hidden vectors -------
    for (int p = tid; p < NPLANE; p += 256) {
        const float* __restrict__ pp = &g_part[p * CHUNKS];
        float s = ((pp[0] + pp[1]) + (pp[2] + pp[3]))
                + ((pp[4] + pp[5]) + (pp[6] + pp[7]));   // fixed order
        pooled_sh[p] = s * (1.0f / (HH * WW));
    }
    __syncthreads();
    if (tid < BB * RR) {
        const int b = tid / RR, jj = tid % RR;
        const float* __restrict__ pb = &pooled_sh[b * DIMC];
        const float* __restrict__ wj = &w1[jj * DIMC];
        float acc = 0.f;
        #pragma unroll 8
        for (int c = 0; c < DIMC; c++) acc = fmaf(pb[c], wj[c], acc);
        acc = gamma[jj] * (acc - rmean[jj]) * rsqrtf(rvar[jj] + EPSV) + beta[jj];
        tsh[tid] = fmaxf(acc, 0.f);
    }
    __syncthreads();

    // ---------------- Phase 3: conv chunk-jobs, descending (L2-hot first) --
    for (int i = nmy - 1; i >= 0; i--) {
        const int j     = cta + i * NCTA;
        const int plane = j >> 3;
        const int chunk = j & 7;
        const int b     = plane / DIMC;
        const int c     = plane % DIMC;

        // 4 live taps: kidx 0..3 = (0,0),(0,1),(0,2),(1,0)
        if (tid < 4) {
            const int o = c * KK9 + tid;
            float acc = b2[o];
            const float* __restrict__ ts = &tsh[b * RR];
            const float* __restrict__ wr = &w2[(size_t)o * RR];
            #pragma unroll
            for (int k = 0; k < RR; k++) acc = fmaf(ts[k], wr[k], acc);
            wsh[tid] = acc;
        }
        __syncthreads();
        const float w00 = wsh[0], w01 = wsh[1], w02 = wsh[2], w10 = wsh[3];
        const float bvv = bias[c];

        const float* __restrict__ in = x + (size_t)plane * HH * WW;
        float* __restrict__ op = out + (size_t)plane * HH * WW;

        const int col0 = lane * 8;              // 32 lanes x 8 cols = full row
        const int y0   = chunk * CH + warp * 4; // each warp: 4 consecutive rows

        // previous-row halo
        float p[8];
        float pm1, pp8;
        if (y0 == 0) {
            #pragma unroll
            for (int q = 0; q < 8; q++) p[q] = 0.f;
            pm1 = 0.f; pp8 = 0.f;
        } else {
            ld256_evict_first(in + (y0 - 1) * WW + col0, p);
            pm1 = __shfl_up_sync(0xffffffffu, p[7], 1);
            if (lane == 0) pm1 = 0.f;
            pp8 = __shfl_down_sync(0xffffffffu, p[0], 1);
            if (lane == 31) pp8 = 0.f;
        }

        #pragma unroll
        for (int r = 0; r < 4; r++) {
            const int y = y0 + r;
            float cv[8];
            ld256_evict_first(in + y * WW + col0, cv);

            float cm1 = __shfl_up_sync(0xffffffffu, cv[7], 1);
            if (lane == 0) cm1 = 0.f;

            float o[8];
            o[0] = fmaf(w00, pm1,  fmaf(w01, p[0], fmaf(w02, p[1], fmaf(w10, cm1, bvv))));
            #pragma unroll
            for (int q = 1; q < 7; q++)
                o[q] = fmaf(w00, p[q-1], fmaf(w01, p[q], fmaf(w02, p[q+1], fmaf(w10, cv[q-1], bvv))));
            o[7] = fmaf(w00, p[6], fmaf(w01, p[7], fmaf(w02, pp8, fmaf(w10, cv[6], bvv))));

            st256_evict_first(op + y * WW + col0, o);

            float nx = __shfl_down_sync(0xffffffffu, cv[0], 1);
            if (lane == 31) nx = 0.f;
            pm1 = cm1;
            pp8 = nx;
            #pragma unroll
            for (int q = 0; q < 8; q++) p[q] = cv[q];
        }
        __syncthreads();   // protect wsh before next job overwrites it
    }

    // ---------------- Reset counters for next graph replay -----------------
    if (tid == 0) {
        unsigned d = atomicAdd(&g_done, 1u);
        if (d == (unsigned)(NCTA - 1)) {
            g_arrive = 0u;
            g_done   = 0u;
            __threadfence();
        }
    }
}

// ---------------------------------------------------------------------------
// Launch. Inputs (metadata order):
//  0:x 1:w1 2:gamma 3:beta 4:running_mean 5:running_var 6:w2 7:b2 8:bias
// ---------------------------------------------------------------------------
extern "C" void kernel_launch(void* const* d_in, const int* in_sizes, int n_in,
                              void* d_out, int out_size) {
    const float* x     = (const float*)d_in[0];
    const float* w1    = (const float*)d_in[1];
    const float* gamma = (const float*)d_in[2];
    const float* beta  = (const float*)d_in[3];
    const float* rmean = (const float*)d_in[4];
    const float* rvar  = (const float*)d_in[5];
    const float* w2    = (const float*)d_in[6];
    const float* b2    = (const float*)d_in[7];
    const float* bias  = (const float*)d_in[8];
    float* out = (float*)d_out;

    fused_kernel<<<NCTA, 256>>>(x, w1, gamma, beta, rmean, rvar, w2, b2, bias, out);
}

// round 13
// speedup vs baseline: 1.0314x; 1.0314x over previous
#include <cuda_runtime.h>

#define DIMC 192
#define BB   4
#define HH   256
#define WW   256
#define RR   48
#define KK9  9
#define EPSV 1e-5f
#define NCTA     592                  // 4 x 148: all resident, 4 CTAs/SM exact
#define NPLANE   (BB * DIMC)          // 768
#define ROWS_TOT (NPLANE * HH)        // 196608 global rows
#define RBASE    (ROWS_TOT / NCTA)    // 332
#define RREM     (ROWS_TOT % NCTA)    // 64

// Scratch (allocation-free rule: __device__ globals; zero-initialized)
__device__ float g_segA[NPLANE];   // partial sum from CTA owning plane start
__device__ float g_segB[NPLANE];   // partial sum from following CTA (or 0)
__device__ unsigned g_arrive;
__device__ unsigned g_done;

// ---- 256-bit L2 eviction-hinted accesses ----------------------------------
__device__ __forceinline__ void ld256_evict_last(const float* p, float* v) {
    asm volatile("ld.global.L2::evict_last.v8.b32 {%0,%1,%2,%3,%4,%5,%6,%7}, [%8];"
                 : "=f"(v[0]), "=f"(v[1]), "=f"(v[2]), "=f"(v[3]),
                   "=f"(v[4]), "=f"(v[5]), "=f"(v[6]), "=f"(v[7])
                 : "l"(p));
}
__device__ __forceinline__ void ld256_evict_first(const float* p, float* v) {
    asm volatile("ld.global.L2::evict_first.v8.b32 {%0,%1,%2,%3,%4,%5,%6,%7}, [%8];"
                 : "=f"(v[0]), "=f"(v[1]), "=f"(v[2]), "=f"(v[3]),
                   "=f"(v[4]), "=f"(v[5]), "=f"(v[6]), "=f"(v[7])
                 : "l"(p));
}
__device__ __forceinline__ void st256_evict_first(float* p, const float* v) {
    asm volatile("st.global.L2::evict_first.v8.b32 [%0], {%1,%2,%3,%4,%5,%6,%7,%8};"
                 :: "l"(p),
                    "f"(v[0]), "f"(v[1]), "f"(v[2]), "f"(v[3]),
                    "f"(v[4]), "f"(v[5]), "f"(v[6]), "f"(v[7])
                 : "memory");
}

// ---------------------------------------------------------------------------
// Fused persistent kernel, contiguous global-row partition (R7 structure,
// 0.3% imbalance):
//   pool own range ascending (evict_last) -> grid barrier -> reduce + MLP +
//   taps for this CTA's <=3 planes -> conv own range DESCENDING per warp
//   (reverse register carry; freshest-pooled rows hit L2 first).
// ---------------------------------------------------------------------------
__global__ __launch_bounds__(256, 4) void fused_kernel(
    const float* __restrict__ x,
    const float* __restrict__ w1,
    const float* __restrict__ gamma,
    const float* __restrict__ beta,
    const float* __restrict__ rmean,
    const float* __restrict__ rvar,
    const float* __restrict__ w2,
    const float* __restrict__ b2,
    const float* __restrict__ bias,
    float* __restrict__ out) {

    const int tid  = threadIdx.x;
    const int warp = tid >> 5;
    const int lane = tid & 31;
    const int cta  = blockIdx.x;

    // contiguous global-row range of this CTA
    const int rs  = cta * RBASE + min(cta, RREM);
    const int rc  = RBASE + (cta < RREM ? 1 : 0);

    __shared__ float pooled_sh[NPLANE];  // per-plane means (3 KB)
    __shared__ float tsh[BB * RR];       // hidden vectors, all 4 batches
    __shared__ float wsh[3][4];          // taps for this CTA's <=3 planes
    __shared__ float bsh[3];             // bias for those planes
    __shared__ float red[8];

    // ---------------- Phase 1: pool own range (evict_last pins x) ----------
    {
        int grow = rs, left = rc;
        while (left > 0) {
            const int plane = grow >> 8;
            const int r0    = grow & 255;
            const int segR  = min(256 - r0, left);
            const float* __restrict__ base = x + (size_t)grow * WW;
            const int nf8 = segR * (WW / 8);

            float s = 0.f;
            for (int i = tid; i < nf8; i += 256) {
                float v[8];
                ld256_evict_last(base + i * 8, v);
                s += ((v[0] + v[1]) + (v[2] + v[3])) + ((v[4] + v[5]) + (v[6] + v[7]));
            }
            #pragma unroll
            for (int o = 16; o > 0; o >>= 1) s += __shfl_down_sync(0xffffffffu, s, o);
            if (lane == 0) red[warp] = s;
            __syncthreads();
            if (tid < 8) {
                float v = red[tid];
                #pragma unroll
                for (int o = 4; o > 0; o >>= 1) v += __shfl_down_sync(0xffu, v, o);
                if (tid == 0) {
                    if (r0 != 0) {
                        // plane started in previous CTA -> second slot
                        g_segB[plane] = v;
                    } else {
                        g_segA[plane] = v;
                        // plane fully inside this CTA -> nobody else writes B
                        if (segR == 256) g_segB[plane] = 0.f;
                    }
                }
            }
            __syncthreads();
            grow += segR;
            left -= segR;
        }
    }

    // ---------------- Grid-wide barrier ------------------------------------
    if (tid == 0) {
        __threadfence();
        atomicAdd(&g_arrive, 1u);
        while (*(volatile unsigned*)&g_arrive < (unsigned)NCTA) { __nanosleep(64); }
        __threadfence();
    }
    __syncthreads();

    // ---------------- Phase 2: reduce, hidden vectors, taps ----------------
    for (int p = tid; p < NPLANE; p += 256)
        pooled_sh[p] = (g_segA[p] + g_segB[p]) * (1.0f / (HH * WW));
    __syncthreads();
    if (tid < BB * RR) {
        const int b = tid / RR, jj = tid % RR;
        const float* __restrict__ pb = &pooled_sh[b * DIMC];
        const float* __restrict__ wj = &w1[jj * DIMC];
        float acc = 0.f;
        #pragma unroll 8
        for (int c = 0; c < DIMC; c++) acc = fmaf(pb[c], wj[c], acc);
        acc = gamma[jj] * (acc - rmean[jj]) * rsqrtf(rvar[jj] + EPSV) + beta[jj];
        tsh[tid] = fmaxf(acc, 0.f);
    }
    __syncthreads();

    const int pFirst = rs >> 8;
    const int pLast  = (rs + rc - 1) >> 8;
    const int nPl    = pLast - pFirst + 1;           // 2 or 3
    if (tid < nPl * 4) {
        const int pi = tid >> 2, k = tid & 3;        // taps kidx 0..3
        const int plane = pFirst + pi;
        const int b = plane / DIMC, c = plane % DIMC;
        const int o = c * KK9 + k;
        float acc = b2[o];
        const float* __restrict__ ts = &tsh[b * RR];
        const float* __restrict__ wr = &w2[(size_t)o * RR];
        #pragma unroll
        for (int j = 0; j < RR; j++) acc = fmaf(ts[j], wr[j], acc);
        wsh[pi][k] = acc;
    }
    if (tid < nPl) bsh[tid] = bias[(pFirst + tid) % DIMC];
    __syncthreads();

    // ---------------- Phase 3: conv own range, descending per warp ---------
    // warp w owns a contiguous sub-range of the CTA's rows
    {
        const int wb   = rc >> 3;                    // base rows per warp
        const int wrem = rc & 7;
        const int ws   = rs + warp * wb + min(warp, wrem);
        const int wcnt = wb + (warp < wrem ? 1 : 0);
        const int yhi  = ws + wcnt - 1;
        const int col0 = lane * 8;

        // taps of the plane of row yhi
        int rel = (yhi >> 8) - pFirst;
        float w00 = wsh[rel][0], w01 = wsh[rel][1],
              w02 = wsh[rel][2], w10 = wsh[rel][3], bvv = bsh[rel];

        // cur = row yhi
        float cur[8];
        ld256_evict_first(x + (size_t)yhi * WW + col0, cur);

        for (int y = yhi; y >= ws; y--) {
            const int r = (y >> 8) - pFirst;
            if (r != rel) {   // warp-uniform plane change (descending)
                rel = r;
                w00 = wsh[rel][0]; w01 = wsh[rel][1];
                w02 = wsh[rel][2]; w10 = wsh[rel][3]; bvv = bsh[rel];
            }
            const bool planeTop = ((y & 255) == 0);

            float up[8];
            if (!planeTop) {
                ld256_evict_first(x + (size_t)(y - 1) * WW + col0, up);
            } else {
                #pragma unroll
                for (int q = 0; q < 8; q++) up[q] = 0.f;
            }

            // halos (within-row, via shfl)
            float um1 = __shfl_up_sync(0xffffffffu, up[7], 1);
            if (lane == 0) um1 = 0.f;
            float up8 = __shfl_down_sync(0xffffffffu, up[0], 1);
            if (lane == 31) up8 = 0.f;
            float cm1 = __shfl_up_sync(0xffffffffu, cur[7], 1);
            if (lane == 0) cm1 = 0.f;

            float o[8];
            o[0] = fmaf(w00, um1,  fmaf(w01, up[0], fmaf(w02, up[1], fmaf(w10, cm1, bvv))));
            #pragma unroll
            for (int q = 1; q < 7; q++)
                o[q] = fmaf(w00, up[q-1], fmaf(w01, up[q], fmaf(w02, up[q+1], fmaf(w10, cur[q-1], bvv))));
            o[7] = fmaf(w00, up[6], fmaf(w01, up[7], fmaf(w02, up8, fmaf(w10, cur[6], bvv))));

            st256_evict_first(out + (size_t)y * WW + col0, o);

            // reverse carry: next iteration's cur is row y-1
            if (planeTop) {
                if (y > ws) ld256_evict_first(x + (size_t)(y - 1) * WW + col0, cur);
            } else {
                #pragma unroll
                for (int q = 0; q < 8; q++) cur[q] = up[q];
            }
        }
    }

    // ---------------- Reset counters for next graph replay -----------------
    if (tid == 0) {
        unsigned d = atomicAdd(&g_done, 1u);
        if (d == (unsigned)(NCTA - 1)) {
            g_arrive = 0u;
            g_done   = 0u;
            __threadfence();
        }
    }
}

// ---------------------------------------------------------------------------
// Launch. Inputs (metadata order):
//  0:x 1:w1 2:gamma 3:beta 4:running_mean 5:running_var 6:w2 7:b2 8:bias
// ---------------------------------------------------------------------------
extern "C" void kernel_launch(void* const* d_in, const int* in_sizes, int n_in,
                              void* d_out, int out_size) {
    const float* x     = (const float*)d_in[0];
    const float* w1    = (const float*)d_in[1];
    const float* gamma = (const float*)d_in[2];
    const float* beta  = (const float*)d_in[3];
    const float* rmean = (const float*)d_in[4];
    const float* rvar  = (const float*)d_in[5];
    const float* w2    = (const float*)d_in[6];
    const float* b2    = (const float*)d_in[7];
    const float* bias  = (const float*)d_in[8];
    float* out = (float*)d_out;

    fused_kernel<<<NCTA, 256>>>(x, w1, gamma, beta, rmean, rvar, w2, b2, bias, out);
}

// round 15
// speedup vs baseline: 1.1357x; 1.1011x over previous
#include <cuda_runtime.h>

#define DIMC 192
#define BB   4
#define HH   256
#define WW   256
#define RR   48
#define KK9  9
#define EPSV 1e-5f
#define NCTA     444                  // 3 x 148: all resident, 3 CTAs/SM exact
#define NPLANE   (BB * DIMC)          // 768
#define ROWS_TOT (NPLANE * HH)        // 196608
#define RBASE    (ROWS_TOT / NCTA)    // 442
#define RREM     (ROWS_TOT % NCTA)    // 360

// Scratch (allocation-free rule: __device__ globals; zero-initialized)
__device__ float g_segA[NPLANE];   // partial from CTA owning plane start
__device__ float g_segB[NPLANE];   // partial from following CTA (or 0)
__device__ unsigned g_arrive;
__device__ unsigned g_done;

// ---- 256-bit L2 eviction-hinted accesses ----------------------------------
__device__ __forceinline__ void ld256_evict_last(const float* p, float* v) {
    asm volatile("ld.global.L2::evict_last.v8.b32 {%0,%1,%2,%3,%4,%5,%6,%7}, [%8];"
                 : "=f"(v[0]), "=f"(v[1]), "=f"(v[2]), "=f"(v[3]),
                   "=f"(v[4]), "=f"(v[5]), "=f"(v[6]), "=f"(v[7])
                 : "l"(p));
}
__device__ __forceinline__ void ld256_evict_first(const float* p, float* v) {
    asm volatile("ld.global.L2::evict_first.v8.b32 {%0,%1,%2,%3,%4,%5,%6,%7}, [%8];"
                 : "=f"(v[0]), "=f"(v[1]), "=f"(v[2]), "=f"(v[3]),
                   "=f"(v[4]), "=f"(v[5]), "=f"(v[6]), "=f"(v[7])
                 : "l"(p));
}
__device__ __forceinline__ void st256_evict_first(float* p, const float* v) {
    asm volatile("st.global.L2::evict_first.v8.b32 [%0], {%1,%2,%3,%4,%5,%6,%7,%8};"
                 :: "l"(p),
                    "f"(v[0]), "f"(v[1]), "f"(v[2]), "f"(v[3]),
                    "f"(v[4]), "f"(v[5]), "f"(v[6]), "f"(v[7])
                 : "memory");
}

// one output row: up = row y-1 regs, cur = row y regs (tap w10 uses cur[q-1])
// um1 = up[-1] halo, up8 = up[8] halo, cm1 = cur[-1] halo
__device__ __forceinline__ void emit_row(
    float* op, int y, int col0,
    const float* up, const float* cur,
    float um1, float up8, float cm1,
    float w00, float w01, float w02, float w10, float bvv) {
    float o[8];
    o[0] = fmaf(w00, um1,  fmaf(w01, up[0], fmaf(w02, up[1], fmaf(w10, cm1, bvv))));
    #pragma unroll
    for (int q = 1; q < 7; q++)
        o[q] = fmaf(w00, up[q-1], fmaf(w01, up[q], fmaf(w02, up[q+1], fmaf(w10, cur[q-1], bvv))));
    o[7] = fmaf(w00, up[6], fmaf(w01, up[7], fmaf(w02, up8, fmaf(w10, cur[6], bvv))));
    st256_evict_first(op + (size_t)y * WW + col0, o);
}

__device__ __forceinline__ float shup(float v, int lane) {
    float r = __shfl_up_sync(0xffffffffu, v, 1);
    return (lane == 0) ? 0.f : r;
}
__device__ __forceinline__ float shdn(float v, int lane) {
    float r = __shfl_down_sync(0xffffffffu, v, 1);
    return (lane == 31) ? 0.f : r;
}

// ---------------------------------------------------------------------------
// Fused persistent kernel. 444 CTAs (3/SM exact), contiguous row ranges
// (0.2% imbalance). Pool ascending (evict_last) -> barrier -> MLP+taps ->
// conv descending per warp: plane-bounded segments, 4-row register groups,
// front-batched independent loads (MLP=4), branch-free bodies.
// ---------------------------------------------------------------------------
__global__ __launch_bounds__(256, 3) void fused_kernel(
    const float* __restrict__ x,
    const float* __restrict__ w1,
    const float* __restrict__ gamma,
    const float* __restrict__ beta,
    const float* __restrict__ rmean,
    const float* __restrict__ rvar,
    const float* __restrict__ w2,
    const float* __restrict__ b2,
    const float* __restrict__ bias,
    float* __restrict__ out) {

    const int tid  = threadIdx.x;
    const int warp = tid >> 5;
    const int lane = tid & 31;
    const int cta  = blockIdx.x;

    const int rs = cta * RBASE + min(cta, RREM);
    const int rc = RBASE + (cta < RREM ? 1 : 0);

    __shared__ float pooled_sh[NPLANE];
    __shared__ float tsh[BB * RR];
    __shared__ float wsh[3][4];
    __shared__ float bsh[3];
    __shared__ float red[8];

    // ---------------- Phase 1: pool own range ascending (evict_last) -------
    {
        int grow = rs, left = rc;
        while (left > 0) {
            const int plane = grow >> 8;
            const int r0    = grow & 255;
            const int segR  = min(256 - r0, left);
            const float* __restrict__ base = x + (size_t)grow * WW;
            const int nf8 = segR * (WW / 8);

            float s = 0.f;
            for (int i = tid; i < nf8; i += 256) {
                float v[8];
                ld256_evict_last(base + i * 8, v);
                s += ((v[0] + v[1]) + (v[2] + v[3])) + ((v[4] + v[5]) + (v[6] + v[7]));
            }
            #pragma unroll
            for (int o = 16; o > 0; o >>= 1) s += __shfl_down_sync(0xffffffffu, s, o);
            if (lane == 0) red[warp] = s;
            __syncthreads();
            if (tid < 8) {
                float v = red[tid];
                #pragma unroll
                for (int o = 4; o > 0; o >>= 1) v += __shfl_down_sync(0xffu, v, o);
                if (tid == 0) {
                    if (r0 != 0) g_segB[plane] = v;
                    else {
                        g_segA[plane] = v;
                        if (segR == 256) g_segB[plane] = 0.f;
                    }
                }
            }
            __syncthreads();
            grow += segR;
            left -= segR;
        }
    }

    // ---------------- Grid-wide barrier ------------------------------------
    if (tid == 0) {
        __threadfence();
        atomicAdd(&g_arrive, 1u);
        while (*(volatile unsigned*)&g_arrive < (unsigned)NCTA) { __nanosleep(64); }
        __threadfence();
    }
    __syncthreads();

    // ---------------- Phase 2: reduce, hidden vectors, taps ----------------
    for (int p = tid; p < NPLANE; p += 256)
        pooled_sh[p] = (g_segA[p] + g_segB[p]) * (1.0f / (HH * WW));
    __syncthreads();
    if (tid < BB * RR) {
        const int b = tid / RR, jj = tid % RR;
        const float* __restrict__ pb = &pooled_sh[b * DIMC];
        const float* __restrict__ wj = &w1[jj * DIMC];
        float acc = 0.f;
        #pragma unroll 8
        for (int c = 0; c < DIMC; c++) acc = fmaf(pb[c], wj[c], acc);
        acc = gamma[jj] * (acc - rmean[jj]) * rsqrtf(rvar[jj] + EPSV) + beta[jj];
        tsh[tid] = fmaxf(acc, 0.f);
    }
    __syncthreads();

    const int pFirst = rs >> 8;
    const int pLast  = (rs + rc - 1) >> 8;
    const int nPl    = pLast - pFirst + 1;        // <= 3
    if (tid < nPl * 4) {
        const int pi = tid >> 2, k = tid & 3;     // live taps kidx 0..3
        const int plane = pFirst + pi;
        const int b = plane / DIMC, c = plane % DIMC;
        const int o = c * KK9 + k;
        float acc = b2[o];
        const float* __restrict__ ts = &tsh[b * RR];
        const float* __restrict__ wr = &w2[(size_t)o * RR];
        #pragma unroll
        for (int j = 0; j < RR; j++) acc = fmaf(ts[j], wr[j], acc);
        wsh[pi][k] = acc;
    }
    if (tid < nPl) bsh[tid] = bias[(pFirst + tid) % DIMC];
    __syncthreads();

    // ---------------- Phase 3: conv own range, descending per warp ---------
    {
        const int wb   = rc >> 3;
        const int wrem = rc & 7;
        const int ws   = rs + warp * wb + min(warp, wrem);
        const int wcnt = wb + (warp < wrem ? 1 : 0);
        const int col0 = lane * 8;

        int y = ws + wcnt - 1;                    // highest row, walk down

        while (y >= ws) {
            // segment: rows [segLo, y] all in one plane
            const int plane = y >> 8;
            const int ptop  = plane << 8;
            const int segLo = (ws > ptop) ? ws : ptop;

            const int rel = plane - pFirst;
            const float w00 = wsh[rel][0], w01 = wsh[rel][1],
                        w02 = wsh[rel][2], w10 = wsh[rel][3];
            const float bvv = bsh[rel];

            float cur[8];
            ld256_evict_first(x + (size_t)y * WW + col0, cur);
            float cm1 = shup(cur[7], lane);       // halo carried down rows

            int nOut = y - segLo;                 // rows emitted via loaded ups

            // 4-row groups: 4 independent front-batched loads (MLP=4)
            while (nOut >= 4) {
                float r1[8], r2[8], r3[8], r4[8];
                ld256_evict_first(x + (size_t)(y - 1) * WW + col0, r1);
                ld256_evict_first(x + (size_t)(y - 2) * WW + col0, r2);
                ld256_evict_first(x + (size_t)(y - 3) * WW + col0, r3);
                ld256_evict_first(x + (size_t)(y - 4) * WW + col0, r4);

                const float m1 = shup(r1[7], lane), p1 = shdn(r1[0], lane);
                const float m2 = shup(r2[7], lane), p2 = shdn(r2[0], lane);
                const float m3 = shup(r3[7], lane), p3 = shdn(r3[0], lane);
                const float m4 = shup(r4[7], lane), p4 = shdn(r4[0], lane);

                emit_row(out, y,     col0, r1, cur, m1, p1, cm1, w00, w01, w02, w10, bvv);
                emit_row(out, y - 1, col0, r2, r1,  m2, p2, m1,  w00, w01, w02, w10, bvv);
                emit_row(out, y - 2, col0, r3, r2,  m3, p3, m2,  w00, w01, w02, w10, bvv);
                emit_row(out, y - 3, col0, r4, r3,  m4, p4, m3,  w00, w01, w02, w10, bvv);

                #pragma unroll
                for (int q = 0; q < 8; q++) cur[q] = r4[q];
                cm1 = m4;
                y -= 4;
                nOut -= 4;
            }
            // single-row remainder (0..3)
            while (nOut > 0) {
                float up[8];
                ld256_evict_first(x + (size_t)(y - 1) * WW + col0, up);
                const float um = shup(up[7], lane), upp = shdn(up[0], lane);
                emit_row(out, y, col0, up, cur, um, upp, cm1, w00, w01, w02, w10, bvv);
                #pragma unroll
                for (int q = 0; q < 8; q++) cur[q] = up[q];
                cm1 = um;
                y--;
                nOut--;
            }
            // final row of segment: y == segLo
            if (segLo == ptop) {
                const float z[8] = {0.f, 0.f, 0.f, 0.f, 0.f, 0.f, 0.f, 0.f};
                emit_row(out, y, col0, z, cur, 0.f, 0.f, cm1, w00, w01, w02, w10, bvv);
            } else {
                float up[8];
                ld256_evict_first(x + (size_t)(y - 1) * WW + col0, up);
                const float um = shup(up[7], lane), upp = shdn(up[0], lane);
                emit_row(out, y, col0, up, cur, um, upp, cm1, w00, w01, w02, w10, bvv);
            }
            y--;
        }
    }

    // ---------------- Reset counters for next graph replay -----------------
    if (tid == 0) {
        unsigned d = atomicAdd(&g_done, 1u);
        if (d == (unsigned)(NCTA - 1)) {
            g_arrive = 0u;
            g_done   = 0u;
            __threadfence();
        }
    }
}

// ---------------------------------------------------------------------------
// Launch. Inputs (metadata order):
//  0:x 1:w1 2:gamma 3:beta 4:running_mean 5:running_var 6:w2 7:b2 8:bias
// ---------------------------------------------------------------------------
extern "C" void kernel_launch(void* const* d_in, const int* in_sizes, int n_in,
                              void* d_out, int out_size) {
    const float* x     = (const float*)d_in[0];
    const float* w1    = (const float*)d_in[1];
    const float* gamma = (const float*)d_in[2];
    const float* beta  = (const float*)d_in[3];
    const float* rmean = (const float*)d_in[4];
    const float* rvar  = (const float*)d_in[5];
    const float* w2    = (const float*)d_in[6];
    const float* b2    = (const float*)d_in[7];
    const float* bias  = (const float*)d_in[8];
    float* out = (float*)d_out;

    fused_kernel<<<NCTA, 256>>>(x, w1, gamma, beta, rmean, rvar, w2, b2, bias, out);
}